// round 5
// baseline (speedup 1.0000x reference)
#include <cuda_runtime.h>
#include <math.h>

#define BATCH  8
#define SEQ    1024
#define DMODEL 1024
#define HEADS  16
#define DHEAD  64
#define TOPK   32
#define BHTOT  (BATCH*HEADS)     // 128
#define NROWS  (BATCH*SEQ)       // 8192

typedef unsigned long long ull;

// ---------------- packed f32x2 helpers (sm_100+) ----------------
__device__ __forceinline__ void fma2(ull &d, ull a, ull b, ull c) {
    asm("fma.rn.f32x2 %0, %1, %2, %3;" : "=l"(d) : "l"(a), "l"(b), "l"(c));
}
__device__ __forceinline__ ull splat2(float x) {
    ull r; asm("mov.b64 %0, {%1, %1};" : "=l"(r) : "f"(x)); return r;
}
__device__ __forceinline__ float2 unpack2(ull v) {
    float2 r; asm("mov.b64 {%0, %1}, %2;" : "=f"(r.x), "=f"(r.y) : "l"(v)); return r;
}

// ---------------- scratch (device globals: allocation-free) ----------------
__device__ float g_q [(size_t)BHTOT*SEQ*DHEAD];   // [b,h,s,d]  32MB
__device__ float g_kT[(size_t)BHTOT*DHEAD*SEQ];   // [b,h,d,s]  32MB
__device__ float g_v [(size_t)BHTOT*SEQ*DHEAD];   // [b,h,s,d]  32MB
__device__ float g_vsum[BHTOT*DHEAD];             // per-(b,h) column sum of v

// ---------------- projection GEMM: C = X[8192,1024]*W[1024,1024]+b ----------
// f32x2-packed, register-double-buffered. Per-output FMA order bitwise
// identical to the scalar R4 kernel (j-adjacent pairs packed in one b64 lane).
// A tile stored DUPLICATED ((v,v) per element) so splats come from LDS.
// MODE 0: write out[((b*H+h)*S+s)*64+d]   (q, v)
// MODE 1: write out[((b*H+h)*64+d)*S+s]   (k transposed)
template<int MODE>
__global__ __launch_bounds__(256, 2) void proj_kernel(
    const float* __restrict__ X, const float* __restrict__ W,
    const float* __restrict__ bias, float* __restrict__ out)
{
    const int BM = 128, BN = 128, BK = 16;
    __shared__ __align__(16) ull   Asd[2][BK][BM];   // duplicated pairs, 32KB
    __shared__ __align__(16) float Bs [2][BK][BN];   // 16KB

    const int row0 = blockIdx.x * BM;
    const int col0 = blockIdx.y * BN;
    const int t  = threadIdx.x;
    const int tx = t & 15, ty = t >> 4;

    const int ar0 = t >> 2, ar1 = (t >> 2) + 64;   // A rows
    const int akg = (t & 3) * 4;                    // A k-group
    const int bk0 = t >> 5, bk1 = (t >> 5) + 8;     // B k rows
    const int bcg = (t & 31) * 4;                   // B col-group

    ull acc2[8][4];
#pragma unroll
    for (int i = 0; i < 8; i++)
#pragma unroll
        for (int j = 0; j < 4; j++) acc2[i][j] = 0ull;

    float4 ra0, ra1, rb0, rb1;

    // prologue: tile 0
    ra0 = *(const float4*)(X + (size_t)(row0 + ar0)*DMODEL + akg);
    ra1 = *(const float4*)(X + (size_t)(row0 + ar1)*DMODEL + akg);
    rb0 = *(const float4*)(W + (size_t)bk0*DMODEL + col0 + bcg);
    rb1 = *(const float4*)(W + (size_t)bk1*DMODEL + col0 + bcg);
    Asd[0][akg+0][ar0] = splat2(ra0.x); Asd[0][akg+1][ar0] = splat2(ra0.y);
    Asd[0][akg+2][ar0] = splat2(ra0.z); Asd[0][akg+3][ar0] = splat2(ra0.w);
    Asd[0][akg+0][ar1] = splat2(ra1.x); Asd[0][akg+1][ar1] = splat2(ra1.y);
    Asd[0][akg+2][ar1] = splat2(ra1.z); Asd[0][akg+3][ar1] = splat2(ra1.w);
    *(float4*)&Bs[0][bk0][bcg] = rb0;
    *(float4*)&Bs[0][bk1][bcg] = rb1;
    __syncthreads();

    int buf = 0;
    for (int k0 = 0; k0 < DMODEL; k0 += BK) {
        const bool has_next = (k0 + BK < DMODEL);
        if (has_next) {
            const int kn = k0 + BK;
            ra0 = *(const float4*)(X + (size_t)(row0 + ar0)*DMODEL + kn + akg);
            ra1 = *(const float4*)(X + (size_t)(row0 + ar1)*DMODEL + kn + akg);
            rb0 = *(const float4*)(W + (size_t)(kn + bk0)*DMODEL + col0 + bcg);
            rb1 = *(const float4*)(W + (size_t)(kn + bk1)*DMODEL + col0 + bcg);
        }

#pragma unroll
        for (int kk = 0; kk < BK; kk++) {
            const ulonglong2* ap2 = (const ulonglong2*)&Asd[buf][kk][ty*8];
            const ulonglong2* bp2 = (const ulonglong2*)&Bs[buf][kk][tx*8];
            ulonglong2 aa0 = ap2[0], aa1 = ap2[1], aa2 = ap2[2], aa3 = ap2[3];
            ulonglong2 bb0 = bp2[0], bb1 = bp2[1];
            ull a2[8] = {aa0.x, aa0.y, aa1.x, aa1.y, aa2.x, aa2.y, aa3.x, aa3.y};
#pragma unroll
            for (int i = 0; i < 8; i++) {
                fma2(acc2[i][0], a2[i], bb0.x, acc2[i][0]);
                fma2(acc2[i][1], a2[i], bb0.y, acc2[i][1]);
                fma2(acc2[i][2], a2[i], bb1.x, acc2[i][2]);
                fma2(acc2[i][3], a2[i], bb1.y, acc2[i][3]);
            }
        }

        if (has_next) {
            const int nb = buf ^ 1;
            Asd[nb][akg+0][ar0] = splat2(ra0.x); Asd[nb][akg+1][ar0] = splat2(ra0.y);
            Asd[nb][akg+2][ar0] = splat2(ra0.z); Asd[nb][akg+3][ar0] = splat2(ra0.w);
            Asd[nb][akg+0][ar1] = splat2(ra1.x); Asd[nb][akg+1][ar1] = splat2(ra1.y);
            Asd[nb][akg+2][ar1] = splat2(ra1.z); Asd[nb][akg+3][ar1] = splat2(ra1.w);
            *(float4*)&Bs[nb][bk0][bcg] = rb0;
            *(float4*)&Bs[nb][bk1][bcg] = rb1;
            __syncthreads();
            buf = nb;
        }
    }

#pragma unroll
    for (int i = 0; i < 8; i++) {
        int row = row0 + ty*8 + i;
        int b = row >> 10, s = row & (SEQ-1);
#pragma unroll
        for (int jj = 0; jj < 4; jj++) {
            float2 p = unpack2(acc2[i][jj]);
#pragma unroll
            for (int u = 0; u < 2; u++) {
                int col = col0 + tx*8 + jj*2 + u;
                float val = (u ? p.y : p.x) + __ldg(bias + col);
                int h = col >> 6, d = col & 63;
                size_t bh = (size_t)b*HEADS + h;
                if (MODE == 0)
                    out[(bh*SEQ + s)*DHEAD + d] = val;
                else
                    out[(bh*DHEAD + d)*SEQ + s] = val;
            }
        }
    }
}

// ---------------- per-(b,h) v column sums (float4) ----------------
__global__ __launch_bounds__(1024) void vsum_kernel()
{
    __shared__ float4 red[1024];
    const int bh = blockIdx.x;
    const int t = threadIdx.x;
    const int dq = t & 15, c = t >> 4;          // 64 s-chunks
    float4 s = make_float4(0.f, 0.f, 0.f, 0.f);
    const float4* vp = (const float4*)(g_v + (size_t)bh*SEQ*DHEAD) + dq;
    for (int si = c; si < SEQ; si += 64) {
        float4 v = vp[(size_t)si*16];
        s.x += v.x; s.y += v.y; s.z += v.z; s.w += v.w;
    }
    red[t] = s;
    __syncthreads();
#pragma unroll
    for (int off = 512; off >= 16; off >>= 1) {
        if (t < off) {
            float4 o = red[t + off];
            red[t].x += o.x; red[t].y += o.y; red[t].z += o.z; red[t].w += o.w;
        }
        __syncthreads();
    }
    if (t < 16)
        *((float4*)(g_vsum + bh*DHEAD) + t) = red[t];
}

// ---------------- fused scores + top-k + context ----------------
#define TQ 16
#define LISTCAP 48
// sc [16][1024] f32 + qsd [64][16] f32x2-dup + ridx/rw [16][48] each
#define ATTN_SMEM_BYTES (TQ*SEQ*4 + DHEAD*TQ*8 + TQ*LISTCAP*8)
static_assert(ATTN_SMEM_BYTES < 227 * 1024, "smem over sm_100a limit");

__global__ __launch_bounds__(256, 2) void attn_kernel(float* __restrict__ out)
{
    extern __shared__ char smemc[];
    float (*sc)[SEQ] = (float(*)[SEQ])smemc;                            // 64KB
    ull   (*qsd)[TQ] = (ull(*)[TQ])(smemc + TQ*SEQ*4);                  // 8KB dup pairs
    int*   ridx      = (int*)(smemc + TQ*SEQ*4 + DHEAD*TQ*8);           // [16][48]
    float* rw        = (float*)(ridx + TQ*LISTCAP);                     // [16][48]

    const int bh = blockIdx.y;
    const int s0 = blockIdx.x * TQ;
    const int t  = threadIdx.x;

    // load q tile, transposed + duplicated into qsd[kk][r] = (q,q)
    {
        int r  = t >> 4;
        int kg = (t & 15) * 4;
        float4 v = *(const float4*)(g_q + ((size_t)bh*SEQ + s0 + r)*DHEAD + kg);
        qsd[kg+0][r] = splat2(v.x); qsd[kg+1][r] = splat2(v.y);
        qsd[kg+2][r] = splat2(v.z); qsd[kg+3][r] = splat2(v.w);
    }
    __syncthreads();

    // ---- scores: thread t computes cols 4t..4t+3, all 16 rows (f32x2) ----
    // per-slot FMA order bitwise identical to scalar version.
    {
        const ulonglong2* kp2 =
            (const ulonglong2*)(g_kT + (size_t)bh*DHEAD*SEQ) + t;   // 16B-aligned
        ull acc2[TQ][2];
#pragma unroll
        for (int r = 0; r < TQ; r++) { acc2[r][0] = 0ull; acc2[r][1] = 0ull; }

        ulonglong2 kv0 = kp2[0];
        ulonglong2 kv1 = kp2[SEQ/4];

#pragma unroll 2
        for (int kk = 0; kk < DHEAD; kk += 2) {
            ulonglong2 n0 = kv0, n1 = kv1;
            if (kk + 2 < DHEAD) {
                n0 = kp2[(size_t)(kk+2)*(SEQ/4)];
                n1 = kp2[(size_t)(kk+3)*(SEQ/4)];
            }
#pragma unroll
            for (int r = 0; r < TQ; r++) {
                ull qd = qsd[kk][r];
                fma2(acc2[r][0], qd, kv0.x, acc2[r][0]);
                fma2(acc2[r][1], qd, kv0.y, acc2[r][1]);
            }
#pragma unroll
            for (int r = 0; r < TQ; r++) {
                ull qd = qsd[kk+1][r];
                fma2(acc2[r][0], qd, kv1.x, acc2[r][0]);
                fma2(acc2[r][1], qd, kv1.y, acc2[r][1]);
            }
            kv0 = n0; kv1 = n1;
        }

        const float scale = 0.125f;   // 1/sqrt(64)
#pragma unroll
        for (int r = 0; r < TQ; r++) {
            float2 p0 = unpack2(acc2[r][0]);
            float2 p1 = unpack2(acc2[r][1]);
            float4 o;
            o.x = p0.x*scale; o.y = p0.y*scale;
            o.z = p1.x*scale; o.w = p1.y*scale;
            *(float4*)&sc[r][4*t] = o;
        }
    }
    __syncthreads();

    // ---- per-row selection + context (1 warp per row, 2 rows per warp) ----
    const int warp = t >> 5, lane = t & 31;
    const int b = bh >> 4, h = bh & 15;

    for (int rr = 0; rr < 2; rr++) {
        const int row = warp*2 + rr;

        // monotonic uint keys, 32 per lane
        unsigned key[32];
#pragma unroll
        for (int i = 0; i < 32; i++) {
            unsigned u = __float_as_uint(sc[row][i*32 + lane]);
            key[i] = (u & 0x80000000u) ? ~u : (u | 0x80000000u);
        }

        // binary-search separating threshold: count(>= thr) == 32
        unsigned lo = 0u, hi = 0xFFFFFFFFu;
        int clo = SEQ;
        while (hi - lo > 1u) {
            unsigned m = lo + ((hi - lo) >> 1);
            int c = 0;
#pragma unroll
            for (int i = 0; i < 32; i++) c += (key[i] >= m);
            c += __shfl_xor_sync(0xFFFFFFFFu, c, 16);
            c += __shfl_xor_sync(0xFFFFFFFFu, c, 8);
            c += __shfl_xor_sync(0xFFFFFFFFu, c, 4);
            c += __shfl_xor_sync(0xFFFFFFFFu, c, 2);
            c += __shfl_xor_sync(0xFFFFFFFFu, c, 1);
            if (c == TOPK) { lo = m; clo = c; break; }
            if (c >  TOPK) { lo = m; clo = c; }
            else           { hi = m; }
        }
        const unsigned thr = lo;
        const int cnt = clo;

        // exp-sum over selected + compact (index, exp(s)-1) lists
        float esum = 0.f;
        int base = 0;
#pragma unroll 1
        for (int i = 0; i < 32; i++) {
            bool p = (key[i] >= thr);
            unsigned mask = __ballot_sync(0xFFFFFFFFu, p);
            if (p) {
                int pos = base + __popc(mask & ((1u << lane) - 1u));
                float sv = sc[row][i*32 + lane];
                float e  = expf(sv);
                esum += e;
                if (pos < LISTCAP) {
                    ridx[row*LISTCAP + pos] = i*32 + lane;
                    rw  [row*LISTCAP + pos] = e - 1.0f;
                }
            }
            base += __popc(mask);
        }
        esum += __shfl_xor_sync(0xFFFFFFFFu, esum, 16);
        esum += __shfl_xor_sync(0xFFFFFFFFu, esum, 8);
        esum += __shfl_xor_sync(0xFFFFFFFFu, esum, 4);
        esum += __shfl_xor_sync(0xFFFFFFFFu, esum, 2);
        esum += __shfl_xor_sync(0xFFFFFFFFu, esum, 1);
        __syncwarp();

        const float denom = esum + (float)(SEQ - cnt) + 1e-8f;
        const float dinv  = 1.0f / denom;

        // context: numerator = vsum + sum_{topk} (exp(s)-1) * v_row
        float a0 = g_vsum[bh*DHEAD + lane];
        float a1 = g_vsum[bh*DHEAD + lane + 32];
        const float* vp = g_v + (size_t)bh*SEQ*DHEAD;
        const int m = cnt < LISTCAP ? cnt : LISTCAP;
        for (int j = 0; j < m; j++) {
            float w   = rw[row*LISTCAP + j];
            int   idx = ridx[row*LISTCAP + j];
            const float* vr = vp + (size_t)idx*DHEAD;
            a0 = fmaf(w, vr[lane],      a0);
            a1 = fmaf(w, vr[lane + 32], a1);
        }
        size_t o = ((size_t)b*SEQ + (s0 + row))*DMODEL + h*DHEAD;
        out[o + lane]      = a0 * dinv;
        out[o + lane + 32] = a1 * dinv;
        __syncwarp();
    }
}

// ---------------- launch ----------------
extern "C" void kernel_launch(void* const* d_in, const int* in_sizes, int n_in,
                              void* d_out, int out_size)
{
    const float* Q  = (const float*)d_in[0];
    const float* K  = (const float*)d_in[1];
    const float* V  = (const float*)d_in[2];
    const float* Wq = (const float*)d_in[3];
    const float* bq = (const float*)d_in[4];
    const float* Wk = (const float*)d_in[5];
    const float* bk = (const float*)d_in[6];
    const float* Wv = (const float*)d_in[7];
    const float* bv = (const float*)d_in[8];
    float* out = (float*)d_out;

    float *q, *kT, *v;
    cudaGetSymbolAddress((void**)&q,  g_q);
    cudaGetSymbolAddress((void**)&kT, g_kT);
    cudaGetSymbolAddress((void**)&v,  g_v);

    (void)cudaFuncSetAttribute(attn_kernel,
                               cudaFuncAttributeMaxDynamicSharedMemorySize,
                               ATTN_SMEM_BYTES);

    dim3 gridP(NROWS/128, DMODEL/128);
    proj_kernel<0><<<gridP, 256>>>(Q, Wq, bq, q);
    proj_kernel<1><<<gridP, 256>>>(K, Wk, bk, kT);
    proj_kernel<0><<<gridP, 256>>>(V, Wv, bv, v);

    vsum_kernel<<<BHTOT, 1024>>>();

    dim3 gridA(SEQ/TQ, BHTOT);
    attn_kernel<<<gridA, 256, ATTN_SMEM_BYTES>>>(out);
}

// round 6
// speedup vs baseline: 1.2100x; 1.2100x over previous
#include <cuda_runtime.h>
#include <math.h>

#define BATCH  8
#define SEQ    1024
#define DMODEL 1024
#define HEADS  16
#define DHEAD  64
#define TOPK   32
#define BHTOT  (BATCH*HEADS)     // 128
#define NROWS  (BATCH*SEQ)       // 8192

// ---------------- scratch (device globals: allocation-free) ----------------
__device__ float g_q [(size_t)BHTOT*SEQ*DHEAD];   // [b,h,s,d]  32MB
__device__ float g_k [(size_t)BHTOT*SEQ*DHEAD];   // [b,h,s,d]  32MB (pre-transpose)
__device__ float g_kT[(size_t)BHTOT*DHEAD*SEQ];   // [b,h,d,s]  32MB
__device__ float g_v [(size_t)BHTOT*SEQ*DHEAD];   // [b,h,s,d]  32MB
__device__ float g_vsum[BHTOT*DHEAD];             // per-(b,h) column sum of v

// ---------------- fused projection GEMM (z = 0:Q 1:K 2:V) -------------------
// C = X[8192,1024]*W[1024,1024]+b, register-double-buffered, scalar FFMA.
// Accumulation order bitwise identical to the R4 kernel. All outputs stored
// coalesced as out[((b*H+h)*S+s)*64+d]; K is transposed by a separate kernel.
__global__ __launch_bounds__(256, 2) void proj_kernel(
    const float* __restrict__ X0, const float* __restrict__ X1,
    const float* __restrict__ X2,
    const float* __restrict__ W0, const float* __restrict__ W1,
    const float* __restrict__ W2,
    const float* __restrict__ b0, const float* __restrict__ b1,
    const float* __restrict__ b2,
    float* __restrict__ o0, float* __restrict__ o1, float* __restrict__ o2)
{
    const int BM = 128, BN = 128, BK = 16;
    __shared__ float As[2][BK][BM];
    __shared__ float Bs[2][BK][BN];

    const int z = blockIdx.z;
    const float* X    = (z == 0) ? X0 : (z == 1) ? X1 : X2;
    const float* W    = (z == 0) ? W0 : (z == 1) ? W1 : W2;
    const float* bias = (z == 0) ? b0 : (z == 1) ? b1 : b2;
    float*       out  = (z == 0) ? o0 : (z == 1) ? o1 : o2;

    const int row0 = blockIdx.x * BM;
    const int col0 = blockIdx.y * BN;
    const int t  = threadIdx.x;
    const int tx = t & 15, ty = t >> 4;

    const int ar0 = t >> 2, ar1 = (t >> 2) + 64;   // A rows
    const int akg = (t & 3) * 4;                    // A k-group
    const int bk0 = t >> 5, bk1 = (t >> 5) + 8;     // B k rows
    const int bcg = (t & 31) * 4;                   // B col-group

    float acc[8][8];
#pragma unroll
    for (int i = 0; i < 8; i++)
#pragma unroll
        for (int j = 0; j < 8; j++) acc[i][j] = 0.f;

    float4 ra0, ra1, rb0, rb1;

    // prologue: tile 0
    ra0 = *(const float4*)(X + (size_t)(row0 + ar0)*DMODEL + akg);
    ra1 = *(const float4*)(X + (size_t)(row0 + ar1)*DMODEL + akg);
    rb0 = *(const float4*)(W + (size_t)bk0*DMODEL + col0 + bcg);
    rb1 = *(const float4*)(W + (size_t)bk1*DMODEL + col0 + bcg);
    As[0][akg+0][ar0] = ra0.x; As[0][akg+1][ar0] = ra0.y;
    As[0][akg+2][ar0] = ra0.z; As[0][akg+3][ar0] = ra0.w;
    As[0][akg+0][ar1] = ra1.x; As[0][akg+1][ar1] = ra1.y;
    As[0][akg+2][ar1] = ra1.z; As[0][akg+3][ar1] = ra1.w;
    *(float4*)&Bs[0][bk0][bcg] = rb0;
    *(float4*)&Bs[0][bk1][bcg] = rb1;
    __syncthreads();

    int buf = 0;
    for (int k0 = 0; k0 < DMODEL; k0 += BK) {
        const bool has_next = (k0 + BK < DMODEL);
        if (has_next) {
            const int kn = k0 + BK;
            ra0 = *(const float4*)(X + (size_t)(row0 + ar0)*DMODEL + kn + akg);
            ra1 = *(const float4*)(X + (size_t)(row0 + ar1)*DMODEL + kn + akg);
            rb0 = *(const float4*)(W + (size_t)(kn + bk0)*DMODEL + col0 + bcg);
            rb1 = *(const float4*)(W + (size_t)(kn + bk1)*DMODEL + col0 + bcg);
        }

#pragma unroll
        for (int kk = 0; kk < BK; kk++) {
            float a[8], b[8];
            *(float4*)(a+0) = *(const float4*)&As[buf][kk][ty*8 + 0];
            *(float4*)(a+4) = *(const float4*)&As[buf][kk][ty*8 + 4];
            *(float4*)(b+0) = *(const float4*)&Bs[buf][kk][tx*8 + 0];
            *(float4*)(b+4) = *(const float4*)&Bs[buf][kk][tx*8 + 4];
#pragma unroll
            for (int i = 0; i < 8; i++)
#pragma unroll
                for (int j = 0; j < 8; j++)
                    acc[i][j] = fmaf(a[i], b[j], acc[i][j]);
        }

        if (has_next) {
            const int nb = buf ^ 1;
            As[nb][akg+0][ar0] = ra0.x; As[nb][akg+1][ar0] = ra0.y;
            As[nb][akg+2][ar0] = ra0.z; As[nb][akg+3][ar0] = ra0.w;
            As[nb][akg+0][ar1] = ra1.x; As[nb][akg+1][ar1] = ra1.y;
            As[nb][akg+2][ar1] = ra1.z; As[nb][akg+3][ar1] = ra1.w;
            *(float4*)&Bs[nb][bk0][bcg] = rb0;
            *(float4*)&Bs[nb][bk1][bcg] = rb1;
            __syncthreads();
            buf = nb;
        }
    }

#pragma unroll
    for (int i = 0; i < 8; i++) {
        int row = row0 + ty*8 + i;
        int b = row >> 10, s = row & (SEQ-1);
#pragma unroll
        for (int j = 0; j < 8; j++) {
            int col = col0 + tx*8 + j;
            float val = acc[i][j] + __ldg(bias + col);
            int h = col >> 6, d = col & 63;
            size_t bh = (size_t)b*HEADS + h;
            out[(bh*SEQ + s)*DHEAD + d] = val;
        }
    }
}

// ---------------- K transpose: g_k[bh][s][d] -> g_kT[bh][d][s] --------------
// 64(s) x 64(d) smem tile, coalesced 128B transactions on both sides.
__global__ __launch_bounds__(256) void ktrans_kernel()
{
    __shared__ float tile[64][65];
    const int bh = blockIdx.x;
    const int s0 = blockIdx.y * 64;
    const int t  = threadIdx.x;

    // read: thread -> row r = t/4, 16 consecutive d at (t&3)*16
    {
        const int r  = t >> 2;
        const int dc = (t & 3) * 16;
        const float4* src =
            (const float4*)(g_k + ((size_t)bh*SEQ + s0 + r)*DHEAD + dc);
#pragma unroll
        for (int i = 0; i < 4; i++) {
            float4 v = src[i];
            tile[r][dc + i*4 + 0] = v.x;
            tile[r][dc + i*4 + 1] = v.y;
            tile[r][dc + i*4 + 2] = v.z;
            tile[r][dc + i*4 + 3] = v.w;
        }
    }
    __syncthreads();

    // write: thread -> d-row dd = t/4, 16 consecutive s at (t&3)*16
    {
        const int dd = t >> 2;
        const int sc = (t & 3) * 16;
        float* dst = g_kT + ((size_t)bh*DHEAD + dd)*SEQ + s0 + sc;
#pragma unroll
        for (int i = 0; i < 4; i++) {
            float4 v;
            v.x = tile[sc + i*4 + 0][dd];
            v.y = tile[sc + i*4 + 1][dd];
            v.z = tile[sc + i*4 + 2][dd];
            v.w = tile[sc + i*4 + 3][dd];
            *(float4*)(dst + i*4) = v;
        }
    }
}

// ---------------- per-(b,h) v column sums (1024 threads) ----------------
__global__ __launch_bounds__(1024) void vsum_kernel()
{
    __shared__ float red[1024];
    const int bh = blockIdx.x;
    const int t = threadIdx.x;
    const int d = t & 63, c = t >> 6;          // 16 s-chunks
    float s = 0.f;
    for (int si = c; si < SEQ; si += 16)
        s += g_v[((size_t)bh*SEQ + si)*DHEAD + d];
    red[t] = s;
    __syncthreads();
    if (t < 512) red[t] += red[t + 512];
    __syncthreads();
    if (t < 256) red[t] += red[t + 256];
    __syncthreads();
    if (t < 128) red[t] += red[t + 128];
    __syncthreads();
    if (t < 64)
        g_vsum[bh*DHEAD + d] = red[t] + red[t + 64];
}

// ---------------- fused scores + top-k + context ----------------
#define TQ 16
#define LISTCAP 48
#define ATTN_SMEM_BYTES ((TQ*SEQ + DHEAD*TQ + TQ*LISTCAP + TQ*LISTCAP) * 4)
static_assert(ATTN_SMEM_BYTES < 227 * 1024, "smem over sm_100a limit");

__global__ __launch_bounds__(256, 2) void attn_kernel(float* __restrict__ out)
{
    extern __shared__ float smem[];
    float (*sc)[SEQ] = (float(*)[SEQ])smem;                        // [16][1024]
    float (*qs)[TQ]  = (float(*)[TQ])(smem + TQ*SEQ);              // [64][16]
    int*   ridx      = (int*)(smem + TQ*SEQ + DHEAD*TQ);           // [16][48]
    float* rw        = (float*)(ridx + TQ*LISTCAP);                // [16][48]

    const int bh = blockIdx.y;
    const int s0 = blockIdx.x * TQ;
    const int t  = threadIdx.x;

    // load q tile, transposed into qs[kk][r]
    {
        int r  = t >> 4;
        int kg = (t & 15) * 4;
        float4 v = *(const float4*)(g_q + ((size_t)bh*SEQ + s0 + r)*DHEAD + kg);
        qs[kg+0][r] = v.x; qs[kg+1][r] = v.y; qs[kg+2][r] = v.z; qs[kg+3][r] = v.w;
    }
    __syncthreads();

    // ---- scores: thread t computes cols 4t..4t+3, all 16 rows ----
    // 2-deep register prefetch of kv; per-kk FMA order identical to R4.
    {
        const float* kp = g_kT + (size_t)bh*DHEAD*SEQ + 4*t;
        float acc[TQ][4];
#pragma unroll
        for (int r = 0; r < TQ; r++)
#pragma unroll
            for (int j = 0; j < 4; j++) acc[r][j] = 0.f;

        float4 kv0 = *(const float4*)(kp);
        float4 kv1 = *(const float4*)(kp + SEQ);

#pragma unroll 2
        for (int kk = 0; kk < DHEAD; kk += 2) {
            float4 n0 = kv0, n1 = kv1;
            if (kk + 2 < DHEAD) {
                n0 = *(const float4*)(kp + (size_t)(kk+2)*SEQ);
                n1 = *(const float4*)(kp + (size_t)(kk+3)*SEQ);
            }
            // kk
            {
                float qv[TQ];
                *(float4*)(qv+0)  = *(const float4*)&qs[kk][0];
                *(float4*)(qv+4)  = *(const float4*)&qs[kk][4];
                *(float4*)(qv+8)  = *(const float4*)&qs[kk][8];
                *(float4*)(qv+12) = *(const float4*)&qs[kk][12];
#pragma unroll
                for (int r = 0; r < TQ; r++) {
                    acc[r][0] = fmaf(qv[r], kv0.x, acc[r][0]);
                    acc[r][1] = fmaf(qv[r], kv0.y, acc[r][1]);
                    acc[r][2] = fmaf(qv[r], kv0.z, acc[r][2]);
                    acc[r][3] = fmaf(qv[r], kv0.w, acc[r][3]);
                }
            }
            // kk+1
            {
                float qv[TQ];
                *(float4*)(qv+0)  = *(const float4*)&qs[kk+1][0];
                *(float4*)(qv+4)  = *(const float4*)&qs[kk+1][4];
                *(float4*)(qv+8)  = *(const float4*)&qs[kk+1][8];
                *(float4*)(qv+12) = *(const float4*)&qs[kk+1][12];
#pragma unroll
                for (int r = 0; r < TQ; r++) {
                    acc[r][0] = fmaf(qv[r], kv1.x, acc[r][0]);
                    acc[r][1] = fmaf(qv[r], kv1.y, acc[r][1]);
                    acc[r][2] = fmaf(qv[r], kv1.z, acc[r][2]);
                    acc[r][3] = fmaf(qv[r], kv1.w, acc[r][3]);
                }
            }
            kv0 = n0; kv1 = n1;
        }

        const float scale = 0.125f;   // 1/sqrt(64)
#pragma unroll
        for (int r = 0; r < TQ; r++) {
            float4 o;
            o.x = acc[r][0]*scale; o.y = acc[r][1]*scale;
            o.z = acc[r][2]*scale; o.w = acc[r][3]*scale;
            *(float4*)&sc[r][4*t] = o;
        }
    }
    __syncthreads();

    // ---- per-row selection + context (1 warp per row, 2 rows per warp) ----
    const int warp = t >> 5, lane = t & 31;
    const int b = bh >> 4, h = bh & 15;

    for (int rr = 0; rr < 2; rr++) {
        const int row = warp*2 + rr;

        // monotonic uint keys, 32 per lane
        unsigned key[32];
#pragma unroll
        for (int i = 0; i < 32; i++) {
            unsigned u = __float_as_uint(sc[row][i*32 + lane]);
            key[i] = (u & 0x80000000u) ? ~u : (u | 0x80000000u);
        }

        // binary-search separating threshold: count(>= thr) == 32
        unsigned lo = 0u, hi = 0xFFFFFFFFu;
        int clo = SEQ;
        while (hi - lo > 1u) {
            unsigned m = lo + ((hi - lo) >> 1);
            int c = 0;
#pragma unroll
            for (int i = 0; i < 32; i++) c += (key[i] >= m);
            c += __shfl_xor_sync(0xFFFFFFFFu, c, 16);
            c += __shfl_xor_sync(0xFFFFFFFFu, c, 8);
            c += __shfl_xor_sync(0xFFFFFFFFu, c, 4);
            c += __shfl_xor_sync(0xFFFFFFFFu, c, 2);
            c += __shfl_xor_sync(0xFFFFFFFFu, c, 1);
            if (c == TOPK) { lo = m; clo = c; break; }
            if (c >  TOPK) { lo = m; clo = c; }
            else           { hi = m; }
        }
        const unsigned thr = lo;
        const int cnt = clo;                   // ==32 except bitwise-tie rows

        // exp-sum over selected + compact (index, exp(s)-1) lists
        float esum = 0.f;
        int base = 0;
#pragma unroll 1
        for (int i = 0; i < 32; i++) {
            bool p = (key[i] >= thr);
            unsigned mask = __ballot_sync(0xFFFFFFFFu, p);
            if (p) {
                int pos = base + __popc(mask & ((1u << lane) - 1u));
                float sv = sc[row][i*32 + lane];
                float e  = expf(sv);
                esum += e;
                if (pos < LISTCAP) {
                    ridx[row*LISTCAP + pos] = i*32 + lane;
                    rw  [row*LISTCAP + pos] = e - 1.0f;
                }
            }
            base += __popc(mask);
        }
        esum += __shfl_xor_sync(0xFFFFFFFFu, esum, 16);
        esum += __shfl_xor_sync(0xFFFFFFFFu, esum, 8);
        esum += __shfl_xor_sync(0xFFFFFFFFu, esum, 4);
        esum += __shfl_xor_sync(0xFFFFFFFFu, esum, 2);
        esum += __shfl_xor_sync(0xFFFFFFFFu, esum, 1);
        __syncwarp();

        const float denom = esum + (float)(SEQ - cnt) + 1e-8f;
        const float dinv  = 1.0f / denom;

        // context: numerator = vsum + sum_{topk} (exp(s)-1) * v_row
        float a0 = g_vsum[bh*DHEAD + lane];
        float a1 = g_vsum[bh*DHEAD + lane + 32];
        const float* vp = g_v + (size_t)bh*SEQ*DHEAD;
        const int m = cnt < LISTCAP ? cnt : LISTCAP;
        for (int j = 0; j < m; j++) {
            float w   = rw[row*LISTCAP + j];
            int   idx = ridx[row*LISTCAP + j];
            const float* vr = vp + (size_t)idx*DHEAD;
            a0 = fmaf(w, vr[lane],      a0);
            a1 = fmaf(w, vr[lane + 32], a1);
        }
        size_t o = ((size_t)b*SEQ + (s0 + row))*DMODEL + h*DHEAD;
        out[o + lane]      = a0 * dinv;
        out[o + lane + 32] = a1 * dinv;
        __syncwarp();
    }
}

// ---------------- launch ----------------
extern "C" void kernel_launch(void* const* d_in, const int* in_sizes, int n_in,
                              void* d_out, int out_size)
{
    const float* Q  = (const float*)d_in[0];
    const float* K  = (const float*)d_in[1];
    const float* V  = (const float*)d_in[2];
    const float* Wq = (const float*)d_in[3];
    const float* bq = (const float*)d_in[4];
    const float* Wk = (const float*)d_in[5];
    const float* bk = (const float*)d_in[6];
    const float* Wv = (const float*)d_in[7];
    const float* bv = (const float*)d_in[8];
    float* out = (float*)d_out;

    float *q, *k, *v;
    cudaGetSymbolAddress((void**)&q, g_q);
    cudaGetSymbolAddress((void**)&k, g_k);
    cudaGetSymbolAddress((void**)&v, g_v);

    (void)cudaFuncSetAttribute(attn_kernel,
                               cudaFuncAttributeMaxDynamicSharedMemorySize,
                               ATTN_SMEM_BYTES);

    dim3 gridP(NROWS/128, DMODEL/128, 3);
    proj_kernel<<<gridP, 256>>>(Q, K, V, Wq, Wk, Wv, bq, bk, bv, q, k, v);

    dim3 gridT(BHTOT, SEQ/64);
    ktrans_kernel<<<gridT, 256>>>();

    vsum_kernel<<<BHTOT, 1024>>>();

    dim3 gridA(SEQ/TQ, BHTOT);
    attn_kernel<<<gridA, 256, ATTN_SMEM_BYTES>>>(out);
}